// round 15
// baseline (speedup 1.0000x reference)
#include <cuda_runtime.h>
#include <cstdint>

// Problem constants (from reference setup_inputs)
#define B 8
#define H 100
#define W 100
#define C 512
#define R 300
#define POOL 7
#define ROWBYTES 2048u                 // C * sizeof(float)
#define STAGES 3

// ---- PTX helpers ----
__device__ __forceinline__ uint32_t smem_u32(const void* p) {
    uint32_t a;
    asm("{ .reg .u64 t; cvta.to.shared.u64 t, %1; cvt.u32.u64 %0, t; }"
        : "=r"(a) : "l"(p));
    return a;
}
__device__ __forceinline__ void mbar_init(uint32_t mbar, uint32_t count) {
    asm volatile("mbarrier.init.shared.b64 [%0], %1;" :: "r"(mbar), "r"(count) : "memory");
}
__device__ __forceinline__ void mbar_expect_tx(uint32_t mbar, uint32_t bytes) {
    asm volatile("mbarrier.arrive.expect_tx.shared.b64 _, [%0], %1;"
                 :: "r"(mbar), "r"(bytes) : "memory");
}
__device__ __forceinline__ void mbar_arrive(uint32_t mbar) {
    asm volatile("mbarrier.arrive.shared.b64 _, [%0];" :: "r"(mbar) : "memory");
}
__device__ __forceinline__ void mbar_wait(uint32_t mbar, uint32_t parity) {
    asm volatile(
        "{\n\t.reg .pred P;\n\t"
        "LW%=:\n\t"
        "mbarrier.try_wait.parity.acquire.cta.shared::cta.b64 P, [%0], %1, 0x989680;\n\t"
        "@!P bra LW%=;\n\t}"
        :: "r"(mbar), "r"(parity) : "memory");
}
__device__ __forceinline__ void bulk_g2s(uint32_t dst, const void* src,
                                         uint32_t bytes, uint32_t mbar) {
    asm volatile(
        "cp.async.bulk.shared::cluster.global.mbarrier::complete_tx::bytes "
        "[%0], [%1], %2, [%3];"
        :: "r"(dst), "l"(src), "r"(bytes), "r"(mbar) : "memory");
}
__device__ __forceinline__ void fence_proxy_async_cta() {
    asm volatile("fence.proxy.async.shared::cta;" ::: "memory");
}

struct __align__(128) Stage {
    float tl[C], tr[C];   // top corner rows: contiguous 4KB in gmem when xhi=xlo+1
};

// grid: (R, POOL, B). One block per (roi, py) row; 7 px cells.
// HYBRID gather: top corners (tl|tr) staged via TMA (async proxy -> smem,
// bypasses L1tex wavefront service); bottom corners (bl, br) via LDG.128
// directly to registers (L1tex path). The two delivery paths run in parallel;
// per-cell cost drops below either single-path floor. 3-stage mbarrier ring.
__global__ __launch_bounds__(128, 12) void roi_align_hybrid_kernel(
    const float* __restrict__ x,     // (B, H, W, C)
    const int*   __restrict__ rois,  // (R, 4): x1, y1, w, h
    float*       __restrict__ out)   // (B, R, 7, 7, C)
{
    __shared__ Stage s_buf[STAGES];
    __shared__ unsigned long long s_full[STAGES], s_empty[STAGES];

    const int r  = blockIdx.x;
    const int py = blockIdx.y;
    const int b  = blockIdx.z;
    const int tid = threadIdx.x;

    const int4 roi = __ldg(((const int4*)rois) + r);
    const int x1 = roi.x, y1 = roi.y, w = roi.z, h = roi.w;

    // --- y axis coords, once per block (replicates JAX fp32 math) ---
    const float sh = (float)h;
    float vy = fmaf((float)py + 0.5f, sh * (1.0f / POOL), -0.5f);
    vy = fminf(fmaxf(vy, 0.0f), sh - 1.0f);
    const float fly = floorf(vy);
    const int   ylo = (int)fly;
    const float fy  = vy - fly;
    const int   yhi = min(ylo + 1, h - 1);

    // x-axis common subexpressions
    const float sw   = (float)w;
    const float stpx = sw * (1.0f / POOL);
    const float clx  = sw - 1.0f;
    const int   xmax = w - 1;

    const unsigned rowl_off = (unsigned)(b * (H * W) + (y1 + ylo) * W) * C;  // top row
    const unsigned rowh_off = (unsigned)(b * (H * W) + (y1 + yhi) * W) * C;  // bottom row
    const unsigned out_base = (unsigned)((b * R + r) * 49 + py * POOL) * C;

    uint32_t fullb[STAGES], emptyb[STAGES], bufa[STAGES];
    #pragma unroll
    for (int s = 0; s < STAGES; ++s) {
        fullb[s]  = smem_u32(&s_full[s]);
        emptyb[s] = smem_u32(&s_empty[s]);
        bufa[s]   = smem_u32(&s_buf[s]);
    }

    // Producer: stage top corner rows (tl|tr) for cell px into stage st.
    auto stage_top = [&](int px, int st) {
        float vx = fmaf((float)px + 0.5f, stpx, -0.5f);
        vx = fminf(fmaxf(vx, 0.0f), clx);
        int xlo = (int)floorf(vx);
        int xhi = min(xlo + 1, xmax);
        const unsigned ol = (unsigned)(x1 + xlo) * C;
        mbar_expect_tx(fullb[st], 2 * ROWBYTES);
        if (xhi == xlo + 1) {
            bulk_g2s(bufa[st], x + rowl_off + ol, 2 * ROWBYTES, fullb[st]);
        } else {
            // clamped (xhi == xlo): duplicate the single column into both slots
            const unsigned oh = (unsigned)(x1 + xhi) * C;
            bulk_g2s(bufa[st],            x + rowl_off + ol, ROWBYTES, fullb[st]);
            bulk_g2s(bufa[st] + ROWBYTES, x + rowl_off + oh, ROWBYTES, fullb[st]);
        }
    };

    if (tid == 0) {
        #pragma unroll
        for (int s = 0; s < STAGES; ++s) {
            mbar_init(fullb[s], 1);
            mbar_init(emptyb[s], 128);
        }
        fence_proxy_async_cta();
    }
    __syncthreads();

    if (tid == 0) {
        stage_top(0, 0);
        stage_top(1, 1);
        stage_top(2, 2);
    }

    const int c = tid * 4;
    const float gy = 1.0f - fy;

    #pragma unroll
    for (int px = 0; px < POOL; ++px) {
        const int st        = px % STAGES;
        const int use       = px / STAGES;
        const uint32_t upar = (uint32_t)(use & 1);

        // x coords for this cell (all threads)
        float vx = fmaf((float)px + 0.5f, stpx, -0.5f);
        vx = fminf(fmaxf(vx, 0.0f), clx);
        float flx = floorf(vx);
        int   xlo = (int)flx;
        const float fx = vx - flx;
        int   xhi = min(xlo + 1, xmax);
        const unsigned ol = (unsigned)(x1 + xlo) * C;
        const unsigned oh = (unsigned)(x1 + xhi) * C;

        // Bottom corners via LDG, issued BEFORE the TMA wait (overlap).
        const float4 bl = *(const float4*)(x + rowh_off + ol + c);
        const float4 br = *(const float4*)(x + rowh_off + oh + c);

        // Top corners from TMA-staged smem.
        mbar_wait(fullb[st], upar);
        const float4 tl = *(const float4*)(&s_buf[st].tl[c]);
        const float4 tr = *(const float4*)(&s_buf[st].tr[c]);

        const float gx = 1.0f - fx;
        const float w_tl = gx * gy;
        const float w_tr = fx * gy;
        const float w_bl = gx * fy;
        const float w_br = fx * fy;

        float4 o;
        o.x = fmaf(br.x, w_br, fmaf(bl.x, w_bl, fmaf(tr.x, w_tr, tl.x * w_tl)));
        o.y = fmaf(br.y, w_br, fmaf(bl.y, w_bl, fmaf(tr.y, w_tr, tl.y * w_tl)));
        o.z = fmaf(br.z, w_br, fmaf(bl.z, w_bl, fmaf(tr.z, w_tr, tl.z * w_tl)));
        o.w = fmaf(br.w, w_br, fmaf(bl.w, w_bl, fmaf(tr.w, w_tr, tl.w * w_tl)));

        // output is never re-read: streaming store
        __stcs((float4*)(out + out_base + (unsigned)px * C + c), o);

        // release this stage's buffer
        mbar_arrive(emptyb[st]);

        // producer refills after the use-th emptying (phase `use` -> parity use&1)
        if (tid == 0 && px + STAGES < POOL) {
            mbar_wait(emptyb[st], upar);
            stage_top(px + STAGES, st);
        }
    }
}

extern "C" void kernel_launch(void* const* d_in, const int* in_sizes, int n_in,
                              void* d_out, int out_size)
{
    const float* x    = (const float*)d_in[0];
    const int*   rois = (const int*)d_in[1];
    float*       out  = (float*)d_out;

    dim3 grid(R, POOL, B);   // 16,800 blocks; z-slowest => per-batch L2 locality
    roi_align_hybrid_kernel<<<grid, 128>>>(x, rois, out);
}

// round 16
// speedup vs baseline: 1.0493x; 1.0493x over previous
#include <cuda_runtime.h>
#include <cstdint>

// Problem constants (from reference setup_inputs)
#define B 8
#define H 100
#define W 100
#define C 512
#define R 300
#define POOL 7
#define ROWBYTES 2048u                 // C * sizeof(float)
#define STAGES 3

// ---- PTX helpers ----
__device__ __forceinline__ uint32_t smem_u32(const void* p) {
    uint32_t a;
    asm("{ .reg .u64 t; cvta.to.shared.u64 t, %1; cvt.u32.u64 %0, t; }"
        : "=r"(a) : "l"(p));
    return a;
}
__device__ __forceinline__ void mbar_init(uint32_t mbar, uint32_t count) {
    asm volatile("mbarrier.init.shared.b64 [%0], %1;" :: "r"(mbar), "r"(count) : "memory");
}
__device__ __forceinline__ void mbar_expect_tx(uint32_t mbar, uint32_t bytes) {
    asm volatile("mbarrier.arrive.expect_tx.shared.b64 _, [%0], %1;"
                 :: "r"(mbar), "r"(bytes) : "memory");
}
__device__ __forceinline__ void mbar_wait(uint32_t mbar, uint32_t parity) {
    asm volatile(
        "{\n\t.reg .pred P;\n\t"
        "LW%=:\n\t"
        "mbarrier.try_wait.parity.acquire.cta.shared::cta.b64 P, [%0], %1, 0x989680;\n\t"
        "@!P bra LW%=;\n\t}"
        :: "r"(mbar), "r"(parity) : "memory");
}
__device__ __forceinline__ void bulk_g2s(uint32_t dst, const void* src,
                                         uint32_t bytes, uint32_t mbar) {
    asm volatile(
        "cp.async.bulk.shared::cluster.global.mbarrier::complete_tx::bytes "
        "[%0], [%1], %2, [%3];"
        :: "r"(dst), "l"(src), "r"(bytes), "r"(mbar) : "memory");
}
__device__ __forceinline__ void fence_proxy_async_cta() {
    asm volatile("fence.proxy.async.shared::cta;" ::: "memory");
}

struct __align__(128) Stage {
    float tl[C], tr[C], bl[C], br[C];   // tl|tr and bl|br contiguous 4KB in gmem
};

// grid: (R, POOL, B). One block per (roi, py) row; 7 px cells.
// R10 pipeline structure (syncthreads double-buffer, proven fastest kernel),
// refined: 3-stage ring + merged 2x4KB TMA copies per cell (tl|tr, bl|br are
// gmem-contiguous since xhi = xlo+1; fallback duplicates on clamp).
__global__ __launch_bounds__(128) void roi_align_tma_kernel(
    const float* __restrict__ x,     // (B, H, W, C)
    const int*   __restrict__ rois,  // (R, 4): x1, y1, w, h
    float*       __restrict__ out)   // (B, R, 7, 7, C)
{
    __shared__ Stage s_buf[STAGES];
    __shared__ unsigned long long s_mbar[STAGES];

    const int r  = blockIdx.x;
    const int py = blockIdx.y;
    const int b  = blockIdx.z;
    const int tid = threadIdx.x;

    const int4 roi = __ldg(((const int4*)rois) + r);
    const int x1 = roi.x, y1 = roi.y, w = roi.z, h = roi.w;

    // --- y axis coords, once per block (replicates JAX fp32 math) ---
    const float sh = (float)h;
    float vy = fmaf((float)py + 0.5f, sh * (1.0f / POOL), -0.5f);
    vy = fminf(fmaxf(vy, 0.0f), sh - 1.0f);
    const float fly = floorf(vy);
    const int   ylo = (int)fly;
    const float fy  = vy - fly;
    const int   yhi = min(ylo + 1, h - 1);

    // x-axis common subexpressions
    const float sw   = (float)w;
    const float stpx = sw * (1.0f / POOL);
    const float clx  = sw - 1.0f;
    const int   xmax = w - 1;

    const unsigned rowl_off = (unsigned)(b * (H * W) + (y1 + ylo) * W) * C;
    const unsigned rowh_off = (unsigned)(b * (H * W) + (y1 + yhi) * W) * C;
    const unsigned out_base = (unsigned)((b * R + r) * 49 + py * POOL) * C;

    uint32_t mb[STAGES], bufa[STAGES];
    #pragma unroll
    for (int s = 0; s < STAGES; ++s) {
        mb[s]   = smem_u32(&s_mbar[s]);
        bufa[s] = smem_u32(&s_buf[s]);
    }

    // Producer staging for cell px into stage st (thread 0 only).
    auto stage = [&](int px, int st) {
        float vx = fmaf((float)px + 0.5f, stpx, -0.5f);
        vx = fminf(fmaxf(vx, 0.0f), clx);
        int xlo = (int)floorf(vx);
        int xhi = min(xlo + 1, xmax);
        const unsigned ol = (unsigned)(x1 + xlo) * C;
        mbar_expect_tx(mb[st], 2 * 4096u);
        if (xhi == xlo + 1) {
            // adjacent columns contiguous: one 4KB copy covers tl|tr (and bl|br)
            bulk_g2s(bufa[st],                x + rowl_off + ol, 4096u, mb[st]);
            bulk_g2s(bufa[st] + 2 * ROWBYTES, x + rowh_off + ol, 4096u, mb[st]);
        } else {
            // clamped: xhi == xlo, duplicate the single column into both slots
            const unsigned oh = (unsigned)(x1 + xhi) * C;
            bulk_g2s(bufa[st],                x + rowl_off + ol, ROWBYTES, mb[st]);
            bulk_g2s(bufa[st] + ROWBYTES,     x + rowl_off + oh, ROWBYTES, mb[st]);
            bulk_g2s(bufa[st] + 2 * ROWBYTES, x + rowh_off + ol, ROWBYTES, mb[st]);
            bulk_g2s(bufa[st] + 3 * ROWBYTES, x + rowh_off + oh, ROWBYTES, mb[st]);
        }
    };

    if (tid == 0) {
        #pragma unroll
        for (int s = 0; s < STAGES; ++s) mbar_init(mb[s], 1);
        fence_proxy_async_cta();
        stage(0, 0);
        stage(1, 1);
        stage(2, 2);
    }
    __syncthreads();

    const int c = tid * 4;
    const float gy = 1.0f - fy;

    #pragma unroll
    for (int px = 0; px < POOL; ++px) {
        const int st        = px % STAGES;
        const uint32_t upar = (uint32_t)((px / STAGES) & 1);

        // x fractional weight for this cell
        float vx = fmaf((float)px + 0.5f, stpx, -0.5f);
        vx = fminf(fmaxf(vx, 0.0f), clx);
        const float fx = vx - floorf(vx);

        mbar_wait(mb[st], upar);

        const float4 tl = *(const float4*)(&s_buf[st].tl[c]);
        const float4 tr = *(const float4*)(&s_buf[st].tr[c]);
        const float4 bl = *(const float4*)(&s_buf[st].bl[c]);
        const float4 br = *(const float4*)(&s_buf[st].br[c]);

        const float gx = 1.0f - fx;
        const float w_tl = gx * gy;
        const float w_tr = fx * gy;
        const float w_bl = gx * fy;
        const float w_br = fx * fy;

        float4 o;
        o.x = fmaf(br.x, w_br, fmaf(bl.x, w_bl, fmaf(tr.x, w_tr, tl.x * w_tl)));
        o.y = fmaf(br.y, w_br, fmaf(bl.y, w_bl, fmaf(tr.y, w_tr, tl.y * w_tl)));
        o.z = fmaf(br.z, w_br, fmaf(bl.z, w_bl, fmaf(tr.z, w_tr, tl.z * w_tl)));
        o.w = fmaf(br.w, w_br, fmaf(bl.w, w_bl, fmaf(tr.w, w_tr, tl.w * w_tl)));

        // output is never re-read: streaming store
        __stcs((float4*)(out + out_base + (unsigned)px * C + c), o);

        __syncthreads();                    // all warps done reading buf[st]
        if (tid == 0 && px + STAGES < POOL) {
            stage(px + STAGES, st);         // refill freed buffer
        }
    }
}

extern "C" void kernel_launch(void* const* d_in, const int* in_sizes, int n_in,
                              void* d_out, int out_size)
{
    const float* x    = (const float*)d_in[0];
    const int*   rois = (const int*)d_in[1];
    float*       out  = (float*)d_out;

    dim3 grid(R, POOL, B);   // 16,800 blocks; z-slowest => per-batch L2 locality
    roi_align_tma_kernel<<<grid, 128>>>(x, rois, out);
}

// round 17
// speedup vs baseline: 1.0645x; 1.0144x over previous
#include <cuda_runtime.h>
#include <cstdint>

// Problem constants (from reference setup_inputs)
#define B 8
#define H 100
#define W 100
#define C 512
#define R 300
#define POOL 7
#define ROWBYTES 2048u                 // C * sizeof(float)
#define STAGES 2

// ---- PTX helpers ----
__device__ __forceinline__ uint32_t smem_u32(const void* p) {
    uint32_t a;
    asm("{ .reg .u64 t; cvta.to.shared.u64 t, %1; cvt.u32.u64 %0, t; }"
        : "=r"(a) : "l"(p));
    return a;
}
__device__ __forceinline__ void mbar_init(uint32_t mbar, uint32_t count) {
    asm volatile("mbarrier.init.shared.b64 [%0], %1;" :: "r"(mbar), "r"(count) : "memory");
}
__device__ __forceinline__ void mbar_expect_tx(uint32_t mbar, uint32_t bytes) {
    asm volatile("mbarrier.arrive.expect_tx.shared.b64 _, [%0], %1;"
                 :: "r"(mbar), "r"(bytes) : "memory");
}
__device__ __forceinline__ void mbar_wait(uint32_t mbar, uint32_t parity) {
    asm volatile(
        "{\n\t.reg .pred P;\n\t"
        "LW%=:\n\t"
        "mbarrier.try_wait.parity.acquire.cta.shared::cta.b64 P, [%0], %1, 0x989680;\n\t"
        "@!P bra LW%=;\n\t}"
        :: "r"(mbar), "r"(parity) : "memory");
}
__device__ __forceinline__ void bulk_g2s(uint32_t dst, const void* src,
                                         uint32_t bytes, uint32_t mbar) {
    asm volatile(
        "cp.async.bulk.shared::cluster.global.mbarrier::complete_tx::bytes "
        "[%0], [%1], %2, [%3];"
        :: "r"(dst), "l"(src), "r"(bytes), "r"(mbar) : "memory");
}
__device__ __forceinline__ void fence_proxy_async_cta() {
    asm volatile("fence.proxy.async.shared::cta;" ::: "memory");
}

struct __align__(128) Stage {
    float tl[C], tr[C], bl[C], br[C];   // tl|tr and bl|br contiguous 4KB in gmem
};

// grid: (R, POOL, B). One block per (roi, py) row; 7 px cells.
// 2-stage syncthreads double-buffer (13 CTAs/SM, ~81% occ) + merged 2x4KB TMA
// copies per cell (tl|tr, bl|br gmem-contiguous since xhi = xlo+1; fallback
// duplicates on clamp). Factored from R16: keep merged copies, restore R10's
// occupancy.
__global__ __launch_bounds__(128, 13) void roi_align_tma_kernel(
    const float* __restrict__ x,     // (B, H, W, C)
    const int*   __restrict__ rois,  // (R, 4): x1, y1, w, h
    float*       __restrict__ out)   // (B, R, 7, 7, C)
{
    __shared__ Stage s_buf[STAGES];
    __shared__ unsigned long long s_mbar[STAGES];

    const int r  = blockIdx.x;
    const int py = blockIdx.y;
    const int b  = blockIdx.z;
    const int tid = threadIdx.x;

    const int4 roi = __ldg(((const int4*)rois) + r);
    const int x1 = roi.x, y1 = roi.y, w = roi.z, h = roi.w;

    // --- y axis coords, once per block (replicates JAX fp32 math) ---
    const float sh = (float)h;
    float vy = fmaf((float)py + 0.5f, sh * (1.0f / POOL), -0.5f);
    vy = fminf(fmaxf(vy, 0.0f), sh - 1.0f);
    const float fly = floorf(vy);
    const int   ylo = (int)fly;
    const float fy  = vy - fly;
    const int   yhi = min(ylo + 1, h - 1);

    // x-axis common subexpressions
    const float sw   = (float)w;
    const float stpx = sw * (1.0f / POOL);
    const float clx  = sw - 1.0f;
    const int   xmax = w - 1;

    const unsigned rowl_off = (unsigned)(b * (H * W) + (y1 + ylo) * W) * C;
    const unsigned rowh_off = (unsigned)(b * (H * W) + (y1 + yhi) * W) * C;
    const unsigned out_base = (unsigned)((b * R + r) * 49 + py * POOL) * C;

    uint32_t mb[STAGES], bufa[STAGES];
    #pragma unroll
    for (int s = 0; s < STAGES; ++s) {
        mb[s]   = smem_u32(&s_mbar[s]);
        bufa[s] = smem_u32(&s_buf[s]);
    }

    // Producer staging for cell px into stage st (thread 0 only).
    auto stage = [&](int px, int st) {
        float vx = fmaf((float)px + 0.5f, stpx, -0.5f);
        vx = fminf(fmaxf(vx, 0.0f), clx);
        int xlo = (int)floorf(vx);
        int xhi = min(xlo + 1, xmax);
        const unsigned ol = (unsigned)(x1 + xlo) * C;
        mbar_expect_tx(mb[st], 2 * 4096u);
        if (xhi == xlo + 1) {
            // adjacent columns contiguous: one 4KB copy covers tl|tr (and bl|br)
            bulk_g2s(bufa[st],                x + rowl_off + ol, 4096u, mb[st]);
            bulk_g2s(bufa[st] + 2 * ROWBYTES, x + rowh_off + ol, 4096u, mb[st]);
        } else {
            // clamped: xhi == xlo, duplicate the single column into both slots
            const unsigned oh = (unsigned)(x1 + xhi) * C;
            bulk_g2s(bufa[st],                x + rowl_off + ol, ROWBYTES, mb[st]);
            bulk_g2s(bufa[st] + ROWBYTES,     x + rowl_off + oh, ROWBYTES, mb[st]);
            bulk_g2s(bufa[st] + 2 * ROWBYTES, x + rowh_off + ol, ROWBYTES, mb[st]);
            bulk_g2s(bufa[st] + 3 * ROWBYTES, x + rowh_off + oh, ROWBYTES, mb[st]);
        }
    };

    if (tid == 0) {
        #pragma unroll
        for (int s = 0; s < STAGES; ++s) mbar_init(mb[s], 1);
        fence_proxy_async_cta();
        stage(0, 0);
        stage(1, 1);
    }
    __syncthreads();

    const int c = tid * 4;
    const float gy = 1.0f - fy;

    #pragma unroll
    for (int px = 0; px < POOL; ++px) {
        const int st        = px & 1;
        const uint32_t upar = (uint32_t)((px >> 1) & 1);

        // x fractional weight for this cell
        float vx = fmaf((float)px + 0.5f, stpx, -0.5f);
        vx = fminf(fmaxf(vx, 0.0f), clx);
        const float fx = vx - floorf(vx);

        mbar_wait(mb[st], upar);

        const float4 tl = *(const float4*)(&s_buf[st].tl[c]);
        const float4 tr = *(const float4*)(&s_buf[st].tr[c]);
        const float4 bl = *(const float4*)(&s_buf[st].bl[c]);
        const float4 br = *(const float4*)(&s_buf[st].br[c]);

        const float gx = 1.0f - fx;
        const float w_tl = gx * gy;
        const float w_tr = fx * gy;
        const float w_bl = gx * fy;
        const float w_br = fx * fy;

        float4 o;
        o.x = fmaf(br.x, w_br, fmaf(bl.x, w_bl, fmaf(tr.x, w_tr, tl.x * w_tl)));
        o.y = fmaf(br.y, w_br, fmaf(bl.y, w_bl, fmaf(tr.y, w_tr, tl.y * w_tl)));
        o.z = fmaf(br.z, w_br, fmaf(bl.z, w_bl, fmaf(tr.z, w_tr, tl.z * w_tl)));
        o.w = fmaf(br.w, w_br, fmaf(bl.w, w_bl, fmaf(tr.w, w_tr, tl.w * w_tl)));

        // output is never re-read: streaming store
        __stcs((float4*)(out + out_base + (unsigned)px * C + c), o);

        __syncthreads();                    // all warps done reading buf[st]
        if (tid == 0 && px + STAGES < POOL) {
            stage(px + STAGES, st);         // refill freed buffer
        }
    }
}

extern "C" void kernel_launch(void* const* d_in, const int* in_sizes, int n_in,
                              void* d_out, int out_size)
{
    const float* x    = (const float*)d_in[0];
    const int*   rois = (const int*)d_in[1];
    float*       out  = (float*)d_out;

    dim3 grid(R, POOL, B);   // 16,800 blocks; z-slowest => per-batch L2 locality
    roi_align_tma_kernel<<<grid, 128>>>(x, rois, out);
}